// round 8
// baseline (speedup 1.0000x reference)
#include <cuda_runtime.h>
#include <cuda_fp16.h>
#include <cstdint>

// COO SpMM: out[src[e], :] += att[e] * X[dst[e], :], D = 128 fp32.
//
// TWO kernels (R7 post-mortem: spmm is ISSUE-bound, build pipeline was
// launch/scan-latency fat):
//   1. prep_scatter: X fp32->fp16 convert (DRAM-stream) fused with direct
//      padded-slot scatter (atomic-bound) -> the two overlap.
//      Slot: g_edge[src*CAP + atomicAdd(count[src])] = (dst, att_f32).
//      No histogram, no scan.
//   2. spmm: warp per node, int2 meta (no decode ALU), int4 meta loads
//      (2 edges/inst), fp16 gather, fp32 FMA, streaming store; resets
//      count[] to keep the zero-invariant across graph replays.
//
// Footprint discipline: hot set = X_half 25.6MB + touched meta ~30MB < L2.
// CAP=80 vs Poisson(32) degrees: E[max deg]~59, P(any overflow)~1e-6
// (clamped defensively).

#define CAP 80
#define N_MAX 131072

__device__ int   g_count[N_MAX];                  // zero-invariant across calls
__device__ int2  g_edge[(size_t)N_MAX * CAP];     // (dst, att bits) slots
__device__ uint2 g_xh[(size_t)N_MAX * 32];        // X fp16: 32 uint2/row

__device__ __forceinline__ bool detect64(const void* edges) {
    const int* w = (const int*)edges;
    return (w[1] == 0 && w[3] == 0 && w[5] == 0);  // ids << 2^31
}

__device__ __forceinline__ unsigned h2_bits(__half2 h) {
    return *reinterpret_cast<unsigned*>(&h);
}

// Fused: convert X -> fp16 (DRAM-stream bound) + direct scatter (atomic bound).
__global__ void prep_scatter_kernel(const float4* __restrict__ X, int N,
                                    const void* __restrict__ edges,
                                    const float* __restrict__ att, int E) {
    int stride = gridDim.x * blockDim.x;
    int tid = blockIdx.x * blockDim.x + threadIdx.x;

    // ---- convert X ----
    int n4 = N * 32;
    for (int i = tid; i < n4; i += stride) {
        float4 v = __ldcs(X + i);
        g_xh[i] = make_uint2(h2_bits(__floats2half2_rn(v.x, v.y)),
                             h2_bits(__floats2half2_rn(v.z, v.w)));
    }

    // ---- direct scatter (2 edges per iteration) ----
    const bool is64 = detect64(edges);
    int half = E >> 1;
    for (int i = tid; i < half; i += stride) {
        int s0, s1, d0, d1;
        if (is64) {
            longlong2 s = __ldcs((const longlong2*)edges + i);
            longlong2 d = __ldcs((const longlong2*)((const long long*)edges + E) + i);
            s0 = (int)s.x; s1 = (int)s.y; d0 = (int)d.x; d1 = (int)d.y;
        } else {
            int2 s = __ldcs((const int2*)edges + i);
            int2 d = __ldcs((const int2*)((const int*)edges + E) + i);
            s0 = s.x; s1 = s.y; d0 = d.x; d1 = d.y;
        }
        float2 a = __ldcs((const float2*)att + i);
        int p0 = atomicAdd(&g_count[s0], 1);
        if (p0 < CAP) g_edge[(size_t)s0 * CAP + p0] = make_int2(d0, __float_as_int(a.x));
        int p1 = atomicAdd(&g_count[s1], 1);
        if (p1 < CAP) g_edge[(size_t)s1 * CAP + p1] = make_int2(d1, __float_as_int(a.y));
    }
    if (tid == 0 && (E & 1)) {
        int e = E - 1;
        int s, d;
        if (is64) {
            s = (int)((const long long*)edges)[e];
            d = (int)((const long long*)edges)[(long long)E + e];
        } else {
            s = ((const int*)edges)[e];
            d = ((const int*)edges)[(long long)E + e];
        }
        int p = atomicAdd(&g_count[s], 1);
        if (p < CAP) g_edge[(size_t)s * CAP + p] = make_int2(d, __float_as_int(att[e]));
    }
}

__device__ __forceinline__ void edge_fma(int dst, float a, int lane, float4& acc) {
    uint2 h = __ldg(&g_xh[(size_t)dst * 32 + lane]);
    float2 lo = __half22float2(*(__half2*)&h.x);
    float2 hi = __half22float2(*(__half2*)&h.y);
    acc.x = fmaf(a, lo.x, acc.x); acc.y = fmaf(a, lo.y, acc.y);
    acc.z = fmaf(a, hi.x, acc.z); acc.w = fmaf(a, hi.y, acc.w);
}

// Warp per node: lane l owns feature quad l. Meta read as int4 (2 edges per
// load, broadcast). fp16 gather 8B/lane (256B/row coalesced), fp32 FMA,
// 8 independent gathers in flight, streaming store. Resets g_count.
__global__ void __launch_bounds__(256) spmm_kernel(float4* __restrict__ out, int N) {
    int lane = threadIdx.x & 31;
    int node = (blockIdx.x * blockDim.x + threadIdx.x) >> 5;
    if (node >= N) return;

    int cnt = g_count[node];
    if (lane == 0) g_count[node] = 0;        // restore zero-invariant
    cnt = min(cnt, CAP);

    const int2* meta = g_edge + (size_t)node * CAP;   // 640B-aligned
    float4 acc = make_float4(0.f, 0.f, 0.f, 0.f);

    int e = 0;
    for (; e + 8 <= cnt; e += 8) {
        int4 p0 = __ldg((const int4*)(meta + e));        // edges e,   e+1
        int4 p1 = __ldg((const int4*)(meta + e + 2));    // edges e+2, e+3
        int4 p2 = __ldg((const int4*)(meta + e + 4));    // edges e+4, e+5
        int4 p3 = __ldg((const int4*)(meta + e + 6));    // edges e+6, e+7
        uint2 h0 = __ldg(&g_xh[(size_t)p0.x * 32 + lane]);
        uint2 h1 = __ldg(&g_xh[(size_t)p0.z * 32 + lane]);
        uint2 h2 = __ldg(&g_xh[(size_t)p1.x * 32 + lane]);
        uint2 h3 = __ldg(&g_xh[(size_t)p1.z * 32 + lane]);
        uint2 h4 = __ldg(&g_xh[(size_t)p2.x * 32 + lane]);
        uint2 h5 = __ldg(&g_xh[(size_t)p2.z * 32 + lane]);
        uint2 h6 = __ldg(&g_xh[(size_t)p3.x * 32 + lane]);
        uint2 h7 = __ldg(&g_xh[(size_t)p3.z * 32 + lane]);
        #pragma unroll
        for (int k = 0; k < 8; k++) {
            uint2 h = (k==0)?h0:(k==1)?h1:(k==2)?h2:(k==3)?h3:(k==4)?h4:(k==5)?h5:(k==6)?h6:h7;
            int ab = (k==0)?p0.y:(k==1)?p0.w:(k==2)?p1.y:(k==3)?p1.w:(k==4)?p2.y:(k==5)?p2.w:(k==6)?p3.y:p3.w;
            float a = __int_as_float(ab);
            float2 lo = __half22float2(*(__half2*)&h.x);
            float2 hi = __half22float2(*(__half2*)&h.y);
            acc.x = fmaf(a, lo.x, acc.x); acc.y = fmaf(a, lo.y, acc.y);
            acc.z = fmaf(a, hi.x, acc.z); acc.w = fmaf(a, hi.y, acc.w);
        }
    }
    for (; e + 2 <= cnt; e += 2) {
        int4 p = __ldg((const int4*)(meta + e));
        edge_fma(p.x, __int_as_float(p.y), lane, acc);
        edge_fma(p.z, __int_as_float(p.w), lane, acc);
    }
    if (e < cnt) {
        int2 m = __ldg(meta + e);
        edge_fma(m.x, __int_as_float(m.y), lane, acc);
    }

    __stcs(out + (size_t)node * 32 + lane, acc);
}

extern "C" void kernel_launch(void* const* d_in, const int* in_sizes, int n_in,
                              void* d_out, int out_size) {
    const void* edges = d_in[0];               // (2, E) int32 or int64
    const float* att = (const float*)d_in[1];  // (E,)
    const float4* X = (const float4*)d_in[3];  // (N, 128) fp32
    float4* out = (float4*)d_out;

    int E = in_sizes[1];
    int N = out_size / 128;

    prep_scatter_kernel<<<2048, 256>>>(X, N, edges, att, E);
    spmm_kernel<<<(N + 7) / 8, 256>>>(out, N);
}

// round 9
// speedup vs baseline: 1.6704x; 1.6704x over previous
#include <cuda_runtime.h>
#include <cuda_fp16.h>
#include <cstdint>

// COO SpMM: out[src[e], :] += att[e] * X[dst[e], :], D = 128 fp32.
//
// Packed CSR via counting sort + fp16 gather. 5 kernels:
//   1. prep_hist: X fp32->fp16 convert (DRAM stream) + src histogram (REDG)
//   2. scan1: per-block (1024) exclusive scan of counts -> g_locex, g_cursor;
//             writes per-block sums; resets g_count (zero-invariant)
//   3. scan2: 1-block exclusive scan of block sums -> g_blockoff
//   4. scatter: global slot = atomicAdd(cursor_local[s]) + blockoff[s>>10]
//   5. spmm: warp-per-node; rowptr reconstructed as locex[i]+blockoff[i>>10];
//            int4 meta loads (2 edges/LDG, even-peeled), fp16 gather, fp32 FMA
//
// PACKED meta only (R3+R8 both showed padded-slot layouts are 4x slower).
// Footprint: X_half 25.6MB + meta 25.6MB + ptrs ~1.6MB = ~53MB << 126MB L2.

#define SCAN_BLK 1024
#define N_MAX 131072
#define E_MAX 3276800
#define NSB_MAX (N_MAX / SCAN_BLK)

__device__ int   g_count[N_MAX];       // histogram; zero-invariant (scan1 resets)
__device__ int   g_locex[N_MAX + 1];   // per-block-local exclusive sums
__device__ int   g_cursor[N_MAX];      // scatter cursor (local-offset based)
__device__ int   g_blocksums[NSB_MAX];
__device__ int   g_blockoff[NSB_MAX];
__device__ __align__(16) int2 g_edge[E_MAX];        // (dst, att bits) packed
__device__ uint2 g_xh[(size_t)N_MAX * 32];          // X fp16: 32 uint2/row

__device__ __forceinline__ bool detect64(const void* edges) {
    const int* w = (const int*)edges;
    return (w[1] == 0 && w[3] == 0 && w[5] == 0);   // ids << 2^31
}

__device__ __forceinline__ unsigned h2_bits(__half2 h) {
    return *reinterpret_cast<unsigned*>(&h);
}

// Fused: convert X -> fp16 (DRAM-stream bound) + histogram src (REDG bound).
__global__ void prep_hist_kernel(const float4* __restrict__ X, int N,
                                 const void* __restrict__ edges, int E) {
    int stride = gridDim.x * blockDim.x;
    int tid = blockIdx.x * blockDim.x + threadIdx.x;

    int n4 = N * 32;
    for (int i = tid; i < n4; i += stride) {
        float4 v = __ldcs(X + i);
        g_xh[i] = make_uint2(h2_bits(__floats2half2_rn(v.x, v.y)),
                             h2_bits(__floats2half2_rn(v.z, v.w)));
    }

    const bool is64 = detect64(edges);
    if (is64) {
        const long long* s = (const long long*)edges;
        for (int e = tid; e < E; e += stride)
            atomicAdd(&g_count[(int)s[e]], 1);      // result unused -> REDG
    } else {
        const int* s = (const int*)edges;
        for (int e = tid; e < E; e += stride)
            atomicAdd(&g_count[s[e]], 1);
    }
}

// Per-block exclusive scan (shfl-based). Writes local exclusive + cursor copy,
// block totals, and resets g_count for the next graph replay.
__global__ void __launch_bounds__(SCAN_BLK) scan1_kernel() {
    __shared__ int wsum[32];
    int lane = threadIdx.x & 31;
    int warp = threadIdx.x >> 5;
    int i = blockIdx.x * SCAN_BLK + threadIdx.x;

    int v = g_count[i];
    g_count[i] = 0;                                 // restore zero-invariant
    int x = v;
    #pragma unroll
    for (int off = 1; off < 32; off <<= 1) {
        int t = __shfl_up_sync(0xFFFFFFFFu, x, off);
        if (lane >= off) x += t;
    }
    if (lane == 31) wsum[warp] = x;
    __syncthreads();
    if (warp == 0) {
        int y = wsum[lane];
        #pragma unroll
        for (int off = 1; off < 32; off <<= 1) {
            int t = __shfl_up_sync(0xFFFFFFFFu, y, off);
            if (lane >= off) y += t;
        }
        wsum[lane] = y;
    }
    __syncthreads();
    int excl = ((warp > 0) ? wsum[warp - 1] : 0) + x - v;   // local exclusive
    g_locex[i] = excl;
    g_cursor[i] = excl;
    if (threadIdx.x == SCAN_BLK - 1) g_blocksums[blockIdx.x] = wsum[31];
}

// Exclusive scan of <=128 block sums.
__global__ void scan2_kernel(int nblocks) {
    __shared__ int sh[128];
    int v = (threadIdx.x < nblocks) ? g_blocksums[threadIdx.x] : 0;
    sh[threadIdx.x] = v;
    __syncthreads();
    #pragma unroll
    for (int off = 1; off < 128; off <<= 1) {
        int t = (threadIdx.x >= off) ? sh[threadIdx.x - off] : 0;
        __syncthreads();
        sh[threadIdx.x] += t;
        __syncthreads();
    }
    if (threadIdx.x < nblocks) g_blockoff[threadIdx.x] = sh[threadIdx.x] - v;
}

__global__ void scatter_kernel(const void* __restrict__ edges,
                               const float* __restrict__ att, int E) {
    const bool is64 = detect64(edges);
    int half = E >> 1;
    int stride = gridDim.x * blockDim.x;
    for (int i = blockIdx.x * blockDim.x + threadIdx.x; i < half; i += stride) {
        int s0, s1, d0, d1;
        if (is64) {
            longlong2 s = __ldcs((const longlong2*)edges + i);
            longlong2 d = __ldcs((const longlong2*)((const long long*)edges + E) + i);
            s0 = (int)s.x; s1 = (int)s.y; d0 = (int)d.x; d1 = (int)d.y;
        } else {
            int2 s = __ldcs((const int2*)edges + i);
            int2 d = __ldcs((const int2*)((const int*)edges + E) + i);
            s0 = s.x; s1 = s.y; d0 = d.x; d1 = d.y;
        }
        float2 a = __ldcs((const float2*)att + i);
        int p0 = atomicAdd(&g_cursor[s0], 1) + __ldg(&g_blockoff[s0 >> 10]);
        g_edge[p0] = make_int2(d0, __float_as_int(a.x));
        int p1 = atomicAdd(&g_cursor[s1], 1) + __ldg(&g_blockoff[s1 >> 10]);
        g_edge[p1] = make_int2(d1, __float_as_int(a.y));
    }
    if (blockIdx.x == 0 && threadIdx.x == 0 && (E & 1)) {
        int e = E - 1;
        int s, d;
        if (is64) {
            s = (int)((const long long*)edges)[e];
            d = (int)((const long long*)edges)[(long long)E + e];
        } else {
            s = ((const int*)edges)[e];
            d = ((const int*)edges)[(long long)E + e];
        }
        int p = atomicAdd(&g_cursor[s], 1) + __ldg(&g_blockoff[s >> 10]);
        g_edge[p] = make_int2(d, __float_as_int(att[e]));
    }
}

__device__ __forceinline__ void edge_fma(int dst, int abits, int lane, float4& acc) {
    uint2 h = __ldg(&g_xh[(size_t)dst * 32 + lane]);
    float a = __int_as_float(abits);
    float2 lo = __half22float2(*(__half2*)&h.x);
    float2 hi = __half22float2(*(__half2*)&h.y);
    acc.x = fmaf(a, lo.x, acc.x); acc.y = fmaf(a, lo.y, acc.y);
    acc.z = fmaf(a, hi.x, acc.z); acc.w = fmaf(a, hi.y, acc.w);
}

// Warp per node. Rowptr = locex[i] + blockoff[i>>10]. Even-peel then int4
// meta loads (2 edges/LDG). fp16 gather (8B/lane = 256B/row coalesced),
// fp32 FMA, 8 independent gathers in flight, streaming store.
__global__ void __launch_bounds__(256) spmm_kernel(float4* __restrict__ out, int N) {
    int lane = threadIdx.x & 31;
    int node = (blockIdx.x * blockDim.x + threadIdx.x) >> 5;
    if (node >= N) return;

    int e   = __ldg(&g_locex[node])     + __ldg(&g_blockoff[node >> 10]);
    int end = __ldg(&g_locex[node + 1]) + __ldg(&g_blockoff[(node + 1) >> 10]);

    float4 acc = make_float4(0.f, 0.f, 0.f, 0.f);

    if ((e & 1) && e < end) {           // peel to 16B alignment
        int2 m = __ldg(&g_edge[e]);
        edge_fma(m.x, m.y, lane, acc);
        e++;
    }
    for (; e + 8 <= end; e += 8) {
        int4 q0 = __ldg((const int4*)(g_edge + e));
        int4 q1 = __ldg((const int4*)(g_edge + e + 2));
        int4 q2 = __ldg((const int4*)(g_edge + e + 4));
        int4 q3 = __ldg((const int4*)(g_edge + e + 6));
        uint2 h0 = __ldg(&g_xh[(size_t)q0.x * 32 + lane]);
        uint2 h1 = __ldg(&g_xh[(size_t)q0.z * 32 + lane]);
        uint2 h2 = __ldg(&g_xh[(size_t)q1.x * 32 + lane]);
        uint2 h3 = __ldg(&g_xh[(size_t)q1.z * 32 + lane]);
        uint2 h4 = __ldg(&g_xh[(size_t)q2.x * 32 + lane]);
        uint2 h5 = __ldg(&g_xh[(size_t)q2.z * 32 + lane]);
        uint2 h6 = __ldg(&g_xh[(size_t)q3.x * 32 + lane]);
        uint2 h7 = __ldg(&g_xh[(size_t)q3.z * 32 + lane]);
        #pragma unroll
        for (int k = 0; k < 8; k++) {
            uint2 h = (k==0)?h0:(k==1)?h1:(k==2)?h2:(k==3)?h3:(k==4)?h4:(k==5)?h5:(k==6)?h6:h7;
            int ab = (k==0)?q0.y:(k==1)?q0.w:(k==2)?q1.y:(k==3)?q1.w:(k==4)?q2.y:(k==5)?q2.w:(k==6)?q3.y:q3.w;
            float a = __int_as_float(ab);
            float2 lo = __half22float2(*(__half2*)&h.x);
            float2 hi = __half22float2(*(__half2*)&h.y);
            acc.x = fmaf(a, lo.x, acc.x); acc.y = fmaf(a, lo.y, acc.y);
            acc.z = fmaf(a, hi.x, acc.z); acc.w = fmaf(a, hi.y, acc.w);
        }
    }
    for (; e + 2 <= end; e += 2) {
        int4 q = __ldg((const int4*)(g_edge + e));
        edge_fma(q.x, q.y, lane, acc);
        edge_fma(q.z, q.w, lane, acc);
    }
    if (e < end) {
        int2 m = __ldg(&g_edge[e]);
        edge_fma(m.x, m.y, lane, acc);
    }

    __stcs(out + (size_t)node * 32 + lane, acc);
}

extern "C" void kernel_launch(void* const* d_in, const int* in_sizes, int n_in,
                              void* d_out, int out_size) {
    const void* edges = d_in[0];               // (2, E) int32 or int64
    const float* att = (const float*)d_in[1];  // (E,)
    const float4* X = (const float4*)d_in[3];  // (N, 128) fp32
    float4* out = (float4*)d_out;

    int E = in_sizes[1];
    int N = out_size / 128;
    int npad = ((N + 1 + SCAN_BLK - 1) / SCAN_BLK) * SCAN_BLK;
    int nsb = npad / SCAN_BLK;                 // <= 128

    prep_hist_kernel<<<2048, 256>>>(X, N, edges, E);
    scan1_kernel<<<nsb, SCAN_BLK>>>();
    scan2_kernel<<<1, 128>>>(nsb);
    scatter_kernel<<<2048, 256>>>(edges, att, E);
    spmm_kernel<<<(N + 7) / 8, 256>>>(out, N);
}

// round 10
// speedup vs baseline: 2.2740x; 1.3614x over previous
#include <cuda_runtime.h>
#include <cuda_fp16.h>
#include <cstdint>

// COO SpMM: out[src[e], :] += att[e] * X[dst[e], :], D = 128 fp32.
//
// R6 champion structure (141.4us), with ONE change: scatter is 4-edge
// unrolled to double outstanding ATOMG->STG chains (scatter measured
// latency-bound: issue 7.1%, occ 83%).
//
//   1. prep_hist: X fp32->fp16 convert + src histogram (counters are a
//      maintained zero-invariant: spmm resets them; statics start zero)
//   2-4. 3-stage exclusive scan -> rowptr + cursor
//   5. scatter packed (dst, att_f32), sorted by src  [4-wide unroll]
//   6. spmm: warp-per-node gather-FMA fp16->fp32, streaming store
//
// PACKED meta only (R3+R8: padded-slot layouts are ~4x slower).
// Footprint: X_half 25.6MB + meta 25.6MB + ptrs ~1.2MB = ~53MB << 126MB L2.

#define SCAN_BLK 1024
#define N_MAX 131072
#define E_MAX 3276800

__device__ int    g_count[N_MAX];     // histogram; zero before & after each call
__device__ int    g_cursor[N_MAX];    // scatter fill cursor
__device__ int    g_rowptr[N_MAX + 1];
__device__ int    g_blocksums[N_MAX / SCAN_BLK];
__device__ int2   g_edge[E_MAX];                    // (dst, att bits)
__device__ uint2  g_xh[(size_t)N_MAX * 32];         // X fp16: 32 uint2/row

__device__ __forceinline__ bool detect64(const void* edges) {
    const int* w = (const int*)edges;
    return (w[1] == 0 && w[3] == 0 && w[5] == 0);   // ids << 2^31
}

__device__ __forceinline__ unsigned h2_bits(__half2 h) {
    return *reinterpret_cast<unsigned*>(&h);
}

// Fused: convert X -> fp16 (DRAM-stream bound) + histogram src (atomic bound).
__global__ void prep_hist_kernel(const float4* __restrict__ X, int N,
                                 const void* __restrict__ edges, int E) {
    int stride = gridDim.x * blockDim.x;
    int tid = blockIdx.x * blockDim.x + threadIdx.x;

    int n4 = N * 32;
    for (int i = tid; i < n4; i += stride) {
        float4 v = __ldcs(X + i);
        g_xh[i] = make_uint2(h2_bits(__floats2half2_rn(v.x, v.y)),
                             h2_bits(__floats2half2_rn(v.z, v.w)));
    }

    const bool is64 = detect64(edges);
    if (is64) {
        const long long* s = (const long long*)edges;
        for (int e = tid; e < E; e += stride)
            atomicAdd(&g_count[(int)s[e]], 1);
    } else {
        const int* s = (const int*)edges;
        for (int e = tid; e < E; e += stride)
            atomicAdd(&g_count[s[e]], 1);
    }
}

__global__ void scan1_kernel() {
    __shared__ int sh[SCAN_BLK];
    int i = blockIdx.x * SCAN_BLK + threadIdx.x;
    int v = g_count[i];
    sh[threadIdx.x] = v;
    __syncthreads();
    #pragma unroll
    for (int off = 1; off < SCAN_BLK; off <<= 1) {
        int t = (threadIdx.x >= off) ? sh[threadIdx.x - off] : 0;
        __syncthreads();
        sh[threadIdx.x] += t;
        __syncthreads();
    }
    g_rowptr[i] = sh[threadIdx.x] - v;
    if (threadIdx.x == SCAN_BLK - 1) g_blocksums[blockIdx.x] = sh[threadIdx.x];
}

__global__ void scan2_kernel(int nblocks) {
    __shared__ int sh[128];
    int v = (threadIdx.x < nblocks) ? g_blocksums[threadIdx.x] : 0;
    sh[threadIdx.x] = v;
    __syncthreads();
    #pragma unroll
    for (int off = 1; off < 128; off <<= 1) {
        int t = (threadIdx.x >= off) ? sh[threadIdx.x - off] : 0;
        __syncthreads();
        sh[threadIdx.x] += t;
        __syncthreads();
    }
    if (threadIdx.x < nblocks) g_blocksums[threadIdx.x] = sh[threadIdx.x] - v;
}

__global__ void scan3_kernel(int npad) {
    int i = blockIdx.x * blockDim.x + threadIdx.x;
    if (i < npad) {
        int r = g_rowptr[i] + g_blocksums[i / SCAN_BLK];
        g_rowptr[i] = r;
        g_cursor[i] = r;
    }
}

// 4-edge-per-iteration scatter: 4 independent ATOMG->STG.64 chains per thread
// in flight against the ~318cyc ATOMG latency.
__global__ void scatter_kernel(const void* __restrict__ edges,
                               const float* __restrict__ att, int E) {
    const bool is64 = detect64(edges);
    int quarter = E >> 2;
    int stride = gridDim.x * blockDim.x;
    for (int i = blockIdx.x * blockDim.x + threadIdx.x; i < quarter; i += stride) {
        int s[4], d[4];
        if (is64) {
            longlong2 sa = __ldcs((const longlong2*)edges + 2 * i);
            longlong2 sb = __ldcs((const longlong2*)edges + 2 * i + 1);
            longlong2 da = __ldcs((const longlong2*)((const long long*)edges + E) + 2 * i);
            longlong2 db = __ldcs((const longlong2*)((const long long*)edges + E) + 2 * i + 1);
            s[0] = (int)sa.x; s[1] = (int)sa.y; s[2] = (int)sb.x; s[3] = (int)sb.y;
            d[0] = (int)da.x; d[1] = (int)da.y; d[2] = (int)db.x; d[3] = (int)db.y;
        } else {
            int4 sv = __ldcs((const int4*)edges + i);
            int4 dv = __ldcs((const int4*)((const int*)edges + E) + i);
            s[0] = sv.x; s[1] = sv.y; s[2] = sv.z; s[3] = sv.w;
            d[0] = dv.x; d[1] = dv.y; d[2] = dv.z; d[3] = dv.w;
        }
        float4 a = __ldcs((const float4*)att + i);
        float av[4] = {a.x, a.y, a.z, a.w};
        int p[4];
        #pragma unroll
        for (int k = 0; k < 4; k++) p[k] = atomicAdd(&g_cursor[s[k]], 1);
        #pragma unroll
        for (int k = 0; k < 4; k++) g_edge[p[k]] = make_int2(d[k], __float_as_int(av[k]));
    }
    // tail: up to 3 edges
    if (blockIdx.x == 0 && threadIdx.x == 0) {
        for (int e = E & ~3; e < E; e++) {
            int s, d;
            if (is64) {
                s = (int)((const long long*)edges)[e];
                d = (int)((const long long*)edges)[(long long)E + e];
            } else {
                s = ((const int*)edges)[e];
                d = ((const int*)edges)[(long long)E + e];
            }
            int p = atomicAdd(&g_cursor[s], 1);
            g_edge[p] = make_int2(d, __float_as_int(att[e]));
        }
    }
}

__device__ __forceinline__ void edge_fma_m(int2 m, uint2 h, float4& acc) {
    float a = __int_as_float(m.y);
    float2 lo = __half22float2(*(__half2*)&h.x);
    float2 hi = __half22float2(*(__half2*)&h.y);
    acc.x = fmaf(a, lo.x, acc.x); acc.y = fmaf(a, lo.y, acc.y);
    acc.z = fmaf(a, hi.x, acc.z); acc.w = fmaf(a, hi.y, acc.w);
}

// Warp per node: lane l owns feature quad l. fp16 gather (8B/lane = 256B/row
// coalesced), fp32 accumulate, streaming store. 8 independent gathers in
// flight. Resets g_count to keep the zero-invariant for the next replay.
__global__ void __launch_bounds__(256) spmm_kernel(float4* __restrict__ out, int N) {
    int lane = threadIdx.x & 31;
    int node = (blockIdx.x * blockDim.x + threadIdx.x) >> 5;
    if (node >= N) return;

    int e = __ldg(&g_rowptr[node]);
    int end = __ldg(&g_rowptr[node + 1]);
    if (lane == 0) g_count[node] = 0;       // restore zero-invariant

    float4 acc = make_float4(0.f, 0.f, 0.f, 0.f);

    for (; e + 8 <= end; e += 8) {
        int2 m[8]; uint2 h[8];
        #pragma unroll
        for (int k = 0; k < 8; k++) m[k] = __ldg(&g_edge[e + k]);
        #pragma unroll
        for (int k = 0; k < 8; k++) h[k] = __ldg(&g_xh[(size_t)m[k].x * 32 + lane]);
        #pragma unroll
        for (int k = 0; k < 8; k++) edge_fma_m(m[k], h[k], acc);
    }
    for (; e + 2 <= end; e += 2) {
        int2 m0 = __ldg(&g_edge[e]);
        int2 m1 = __ldg(&g_edge[e + 1]);
        uint2 h0 = __ldg(&g_xh[(size_t)m0.x * 32 + lane]);
        uint2 h1 = __ldg(&g_xh[(size_t)m1.x * 32 + lane]);
        edge_fma_m(m0, h0, acc);
        edge_fma_m(m1, h1, acc);
    }
    if (e < end) {
        int2 m = __ldg(&g_edge[e]);
        uint2 h = __ldg(&g_xh[(size_t)m.x * 32 + lane]);
        edge_fma_m(m, h, acc);
    }

    __stcs(out + (size_t)node * 32 + lane, acc);
}

extern "C" void kernel_launch(void* const* d_in, const int* in_sizes, int n_in,
                              void* d_out, int out_size) {
    const void* edges = d_in[0];               // (2, E) int32 or int64
    const float* att = (const float*)d_in[1];  // (E,)
    const float4* X = (const float4*)d_in[3];  // (N, 128) fp32
    float4* out = (float4*)d_out;

    int E = in_sizes[1];
    int N = out_size / 128;
    int npad = ((N + 1 + SCAN_BLK - 1) / SCAN_BLK) * SCAN_BLK;
    int nsb = npad / SCAN_BLK;

    prep_hist_kernel<<<2048, 256>>>(X, N, edges, E);
    scan1_kernel<<<nsb, SCAN_BLK>>>();
    scan2_kernel<<<1, 128>>>(nsb);
    scan3_kernel<<<(npad + 255) / 256, 256>>>(npad);
    scatter_kernel<<<2048, 256>>>(edges, att, E);
    spmm_kernel<<<(N + 7) / 8, 256>>>(out, N);
}